// round 1
// baseline (speedup 1.0000x reference)
#include <cuda_runtime.h>
#include <math.h>

// Problem constants (fixed by setup_inputs)
#define NB   64      // batch
#define NCH  125     // channels = A*(5+NC)
#define NH   52
#define NW   52
#define NHW  2704    // 52*52
#define NA   5       // anchors
#define NCLS 20      // classes
#define NM   32      // gt boxes per image
#define SCALE 32.0f  // img / H = 1664/52

__device__ __forceinline__ float sigmoidf_(float v) {
    return 1.0f / (1.0f + expf(-v));
}

__global__ void zero_out_kernel(float* out) {
    if (threadIdx.x < 3) out[threadIdx.x] = 0.0f;
}

__global__ __launch_bounds__(256) void yolo_loss_kernel(
    const float* __restrict__ x,
    const float* __restrict__ anchors,
    const float* __restrict__ gt_boxes,
    const int*   __restrict__ gt_labels,
    float* __restrict__ out)
{
    __shared__ float s_gt[NM * 4];
    __shared__ float s_ag[NM];      // gt areas
    __shared__ int   s_lab[NM];
    __shared__ float s_anc[NA * 2];
    __shared__ float s_red[3][8];   // per-warp partials, 8 warps

    const int n   = blockIdx.y;
    const int tid = threadIdx.x;

    if (tid < NM * 4) s_gt[tid] = gt_boxes[n * NM * 4 + tid];
    if (tid < NM)     s_lab[tid] = gt_labels[n * NM + tid];
    if (tid < NA * 2) s_anc[tid] = anchors[tid];
    __syncthreads();
    if (tid < NM) {
        s_ag[tid] = (s_gt[tid*4+2] - s_gt[tid*4+0]) * (s_gt[tid*4+3] - s_gt[tid*4+1]);
    }
    __syncthreads();

    float L0 = 0.0f, L1 = 0.0f, L2 = 0.0f;

    const int cell = blockIdx.x * blockDim.x + tid;
    if (cell < NHW) {
        const int h = cell / NW;
        const int w = cell - h * NW;
        const float* xp = x + (size_t)n * NCH * NHW + cell;

        float px0[NA], py0[NA], px1[NA], py1[NA], bo[NA], ap[NA];

        #pragma unroll
        for (int a = 0; a < NA; a++) {
            const float* cp = xp + (size_t)(a * 25) * NHW;
            float t0 = cp[0 * NHW];
            float t1 = cp[1 * NHW];
            float t2 = cp[2 * NHW];
            float t3 = cp[3 * NHW];
            float t4 = cp[4 * NHW];
            float bx = (float)w * SCALE + sigmoidf_(t0);
            float by = (float)h * SCALE + sigmoidf_(t1);
            float bw = SCALE * s_anc[a * 2 + 0] * expf(t2);
            float bh = SCALE * s_anc[a * 2 + 1] * expf(t3);
            px0[a] = bx;       py0[a] = by;
            px1[a] = bx + bw;  py1[a] = by + bh;
            bo[a]  = sigmoidf_(t4);
            ap[a]  = bw * bh;
        }

        // Per-anchor (max over m, first argmax over m) of IoU
        float amax[NA];
        int   aarg[NA];
        #pragma unroll
        for (int a = 0; a < NA; a++) {
            float mx = -1e30f;
            int   mi = 0;
            #pragma unroll 4
            for (int m = 0; m < NM; m++) {
                float gx0 = s_gt[m*4+0], gy0 = s_gt[m*4+1];
                float gx1 = s_gt[m*4+2], gy1 = s_gt[m*4+3];
                float ltx = fmaxf(px0[a], gx0);
                float lty = fmaxf(py0[a], gy0);
                float rbx = fminf(px1[a], gx1);
                float rby = fminf(py1[a], gy1);
                float iw = fmaxf(rbx - ltx, 0.0f);
                float ih = fmaxf(rby - lty, 0.0f);
                float inter = iw * ih;
                float iou = inter / (ap[a] + s_ag[m] - inter);
                if (iou > mx) { mx = iou; mi = m; }
            }
            amax[a] = mx;
            aarg[a] = mi;
        }

        // best_a = argmax_a amax (first occurrence)
        int   best = 0;
        float bmax = amax[0];
        #pragma unroll
        for (int a = 1; a < NA; a++) {
            if (amax[a] > bmax) { bmax = amax[a]; best = a; }
        }
        const float max_iou = bmax;          // = iou_best.max()
        const int   gt_idx  = aarg[best];    // = argmax_m iou[best, m]
        const bool  sel     = (bmax > 0.0f); // cell_sel

        // objectness loss
        if (sel) {
            float d = bo[best] - max_iou;
            L0 = d * d;
        } else {
            float mb = bo[0];
            #pragma unroll
            for (int a = 1; a < NA; a++) mb = fmaxf(mb, bo[a]);
            L0 = 0.5f * mb * mb;
        }

        if (sel) {
            // bbox loss
            float gx0 = s_gt[gt_idx*4+0], gy0 = s_gt[gt_idx*4+1];
            float gx1 = s_gt[gt_idx*4+2], gy1 = s_gt[gt_idx*4+3];
            float dx = px0[best] - gx0;
            float dy = py0[best] - gy0;
            float dw = sqrtf(px1[best]) - sqrtf(gx1);
            float dh = sqrtf(py1[best]) - sqrtf(gy1);
            L1 = dx*dx + dy*dy + dw*dw + dh*dh;

            // classification loss: CE of log_softmax over 20 scores of best anchor
            const float* sp = xp + (size_t)(best * 25 + 5) * NHW;
            float s[NCLS];
            float mx = -1e30f;
            #pragma unroll
            for (int c = 0; c < NCLS; c++) {
                s[c] = sp[(size_t)c * NHW];
                mx = fmaxf(mx, s[c]);
            }
            float sum = 0.0f;
            #pragma unroll
            for (int c = 0; c < NCLS; c++) sum += expf(s[c] - mx);
            float lse = mx + logf(sum);
            L2 = lse - s[s_lab[gt_idx]];
        }
    }

    // Block reduction: warp shuffle then cross-warp via smem
    const unsigned FULL = 0xFFFFFFFFu;
    #pragma unroll
    for (int off = 16; off > 0; off >>= 1) {
        L0 += __shfl_down_sync(FULL, L0, off);
        L1 += __shfl_down_sync(FULL, L1, off);
        L2 += __shfl_down_sync(FULL, L2, off);
    }
    const int wid = tid >> 5;
    const int lid = tid & 31;
    if (lid == 0) {
        s_red[0][wid] = L0;
        s_red[1][wid] = L1;
        s_red[2][wid] = L2;
    }
    __syncthreads();
    if (wid == 0) {
        float v0 = (lid < 8) ? s_red[0][lid] : 0.0f;
        float v1 = (lid < 8) ? s_red[1][lid] : 0.0f;
        float v2 = (lid < 8) ? s_red[2][lid] : 0.0f;
        #pragma unroll
        for (int off = 4; off > 0; off >>= 1) {
            v0 += __shfl_down_sync(FULL, v0, off);
            v1 += __shfl_down_sync(FULL, v1, off);
            v2 += __shfl_down_sync(FULL, v2, off);
        }
        if (lid == 0) {
            atomicAdd(&out[0], v0);
            atomicAdd(&out[1], v1);
            atomicAdd(&out[2], v2);
        }
    }
}

extern "C" void kernel_launch(void* const* d_in, const int* in_sizes, int n_in,
                              void* d_out, int out_size) {
    const float* x         = (const float*)d_in[0];
    const float* anchors   = (const float*)d_in[1];
    const float* gt_boxes  = (const float*)d_in[2];
    const int*   gt_labels = (const int*)d_in[3];
    float* out = (float*)d_out;

    zero_out_kernel<<<1, 32>>>(out);
    dim3 grid((NHW + 255) / 256, NB);
    yolo_loss_kernel<<<grid, 256>>>(x, anchors, gt_boxes, gt_labels, out);
}

// round 2
// speedup vs baseline: 2.3579x; 2.3579x over previous
#include <cuda_runtime.h>
#include <math.h>

// Problem constants (fixed by setup_inputs)
#define NB   64      // batch
#define NCH  125     // channels = A*(5+NC)
#define NH   52
#define NW   52
#define NHW  2704    // 52*52
#define NA   5       // anchors
#define NCLS 20      // classes
#define NM   32      // gt boxes per image
#define SCALE 32.0f  // img / H = 1664/52

__device__ __forceinline__ float fast_sigmoid(float v) {
    // 1/(1+e^-v) : MUFU.EX2 + FADD + MUFU.RCP
    return __frcp_rn(1.0f + __expf(-v));
}

__global__ void zero_out_kernel(float* out) {
    if (threadIdx.x < 3) out[threadIdx.x] = 0.0f;
}

__global__ __launch_bounds__(256) void yolo_loss_kernel(
    const float* __restrict__ x,
    const float* __restrict__ anchors,
    const float* __restrict__ gt_boxes,
    const int*   __restrict__ gt_labels,
    float* __restrict__ out)
{
    __shared__ float s_gt[NM * 4];
    __shared__ float s_ag[NM];      // gt areas
    __shared__ int   s_lab[NM];
    __shared__ float s_anc[NA * 2];
    __shared__ float s_red[3][8];   // per-warp partials, 8 warps

    const int n   = blockIdx.y;
    const int tid = threadIdx.x;

    if (tid < NM * 4) s_gt[tid] = gt_boxes[n * NM * 4 + tid];
    if (tid < NM)     s_lab[tid] = gt_labels[n * NM + tid];
    if (tid < NA * 2) s_anc[tid] = anchors[tid];
    __syncthreads();
    if (tid < NM) {
        s_ag[tid] = (s_gt[tid*4+2] - s_gt[tid*4+0]) * (s_gt[tid*4+3] - s_gt[tid*4+1]);
    }
    __syncthreads();

    float L0 = 0.0f, L1 = 0.0f, L2 = 0.0f;

    const int cell = blockIdx.x * blockDim.x + tid;
    if (cell < NHW) {
        const int h = cell / NW;
        const int w = cell - h * NW;
        const float* xp = x + (size_t)n * NCH * NHW + cell;

        float px0[NA], py0[NA], px1[NA], py1[NA], bo[NA], ap[NA];

        #pragma unroll
        for (int a = 0; a < NA; a++) {
            const float* cp = xp + (size_t)(a * 25) * NHW;
            float t0 = cp[0 * NHW];
            float t1 = cp[1 * NHW];
            float t2 = cp[2 * NHW];
            float t3 = cp[3 * NHW];
            float t4 = cp[4 * NHW];
            float bx = (float)w * SCALE + fast_sigmoid(t0);
            float by = (float)h * SCALE + fast_sigmoid(t1);
            float bw = SCALE * s_anc[a * 2 + 0] * __expf(t2);
            float bh = SCALE * s_anc[a * 2 + 1] * __expf(t3);
            px0[a] = bx;       py0[a] = by;
            px1[a] = bx + bw;  py1[a] = by + bh;
            bo[a]  = fast_sigmoid(t4);
            ap[a]  = bw * bh;
        }

        // Per-anchor running (max over m, first argmax over m) of IoU,
        // represented as a fraction (inter, den) to avoid 160 divisions.
        // den = area_p + area_g - inter > 0 always, so
        //   iou_m > iou_best  <=>  inter_m * den_best > inter_best * den_m.
        float ibst[NA], dbst[NA];
        int   marg[NA];
        #pragma unroll
        for (int a = 0; a < NA; a++) { ibst[a] = -1.0f; dbst[a] = 1.0f; marg[a] = 0; }

        #pragma unroll 4
        for (int m = 0; m < NM; m++) {
            const float gx0 = s_gt[m*4+0], gy0 = s_gt[m*4+1];
            const float gx1 = s_gt[m*4+2], gy1 = s_gt[m*4+3];
            const float ag  = s_ag[m];
            #pragma unroll
            for (int a = 0; a < NA; a++) {
                float ltx = fmaxf(px0[a], gx0);
                float lty = fmaxf(py0[a], gy0);
                float rbx = fminf(px1[a], gx1);
                float rby = fminf(py1[a], gy1);
                float iw = fmaxf(rbx - ltx, 0.0f);
                float ih = fmaxf(rby - lty, 0.0f);
                float inter = iw * ih;
                float den = (ap[a] + ag) - inter;
                if (inter * dbst[a] > ibst[a] * den) {
                    ibst[a] = inter; dbst[a] = den; marg[a] = m;
                }
            }
        }

        // best_a = argmax_a of per-anchor max IoU (first occurrence), cross-mult
        int best = 0;
        #pragma unroll
        for (int a = 1; a < NA; a++) {
            if (ibst[a] * dbst[best] > ibst[best] * dbst[a]) best = a;
        }
        const float max_iou = ibst[best] / dbst[best];
        const int   gt_idx  = marg[best];
        const bool  sel     = (ibst[best] > 0.0f);   // iou > 0

        // objectness loss
        if (sel) {
            float d = bo[best] - max_iou;
            L0 = d * d;
        } else {
            float mb = bo[0];
            #pragma unroll
            for (int a = 1; a < NA; a++) mb = fmaxf(mb, bo[a]);
            L0 = 0.5f * mb * mb;
        }

        if (sel) {
            // bbox loss
            float gx0 = s_gt[gt_idx*4+0], gy0 = s_gt[gt_idx*4+1];
            float gx1 = s_gt[gt_idx*4+2], gy1 = s_gt[gt_idx*4+3];
            float dx = px0[best] - gx0;
            float dy = py0[best] - gy0;
            float dw = sqrtf(px1[best]) - sqrtf(gx1);
            float dh = sqrtf(py1[best]) - sqrtf(gy1);
            L1 = dx*dx + dy*dy + dw*dw + dh*dh;

            // classification loss: CE of log_softmax over 20 scores of best anchor
            const float* sp = xp + (size_t)(best * 25 + 5) * NHW;
            float s[NCLS];
            float mx = -1e30f;
            #pragma unroll
            for (int c = 0; c < NCLS; c++) {
                s[c] = sp[(size_t)c * NHW];
                mx = fmaxf(mx, s[c]);
            }
            float sum = 0.0f;
            #pragma unroll
            for (int c = 0; c < NCLS; c++) sum += __expf(s[c] - mx);
            float lse = mx + __logf(sum);
            L2 = lse - s[s_lab[gt_idx]];
        }
    }

    // Block reduction: warp shuffle then cross-warp via smem
    const unsigned FULL = 0xFFFFFFFFu;
    #pragma unroll
    for (int off = 16; off > 0; off >>= 1) {
        L0 += __shfl_down_sync(FULL, L0, off);
        L1 += __shfl_down_sync(FULL, L1, off);
        L2 += __shfl_down_sync(FULL, L2, off);
    }
    const int wid = tid >> 5;
    const int lid = tid & 31;
    if (lid == 0) {
        s_red[0][wid] = L0;
        s_red[1][wid] = L1;
        s_red[2][wid] = L2;
    }
    __syncthreads();
    if (wid == 0) {
        float v0 = (lid < 8) ? s_red[0][lid] : 0.0f;
        float v1 = (lid < 8) ? s_red[1][lid] : 0.0f;
        float v2 = (lid < 8) ? s_red[2][lid] : 0.0f;
        #pragma unroll
        for (int off = 4; off > 0; off >>= 1) {
            v0 += __shfl_down_sync(FULL, v0, off);
            v1 += __shfl_down_sync(FULL, v1, off);
            v2 += __shfl_down_sync(FULL, v2, off);
        }
        if (lid == 0) {
            atomicAdd(&out[0], v0);
            atomicAdd(&out[1], v1);
            atomicAdd(&out[2], v2);
        }
    }
}

extern "C" void kernel_launch(void* const* d_in, const int* in_sizes, int n_in,
                              void* d_out, int out_size) {
    const float* x         = (const float*)d_in[0];
    const float* anchors   = (const float*)d_in[1];
    const float* gt_boxes  = (const float*)d_in[2];
    const int*   gt_labels = (const int*)d_in[3];
    float* out = (float*)d_out;

    zero_out_kernel<<<1, 32>>>(out);
    dim3 grid((NHW + 255) / 256, NB);
    yolo_loss_kernel<<<grid, 256>>>(x, anchors, gt_boxes, gt_labels, out);
}